// round 1
// baseline (speedup 1.0000x reference)
#include <cuda_runtime.h>
#include <cstdint>

#define HIDDEN   256
#define NHL      4
#define MTILE    64
#define KS       32
#define NSLAB    8          // HIDDEN / KS
#define THREADS  256

// smem layout (floats): xa[64*256] xb[64*256] wbuf[2*32*256] omg[64] cs[64*4] wfs[256]
#define SMEM_FLOATS (MTILE*HIDDEN*2 + 2*KS*HIDDEN + MTILE + MTILE*4 + HIDDEN)

__device__ __forceinline__ void cp_async16(float* dst, const float4* src) {
    uint32_t s = (uint32_t)__cvta_generic_to_shared(dst);
    asm volatile("cp.async.cg.shared.global [%0], [%1], 16;\n" :: "r"(s), "l"(src));
}
__device__ __forceinline__ void cp_commit() { asm volatile("cp.async.commit_group;\n" ::); }
template<int W> __device__ __forceinline__ void cp_wait() {
    asm volatile("cp.async.wait_group %0;\n" :: "n"(W));
}

// sin with Cody-Waite range reduction to [-pi,pi]; abs err ~3e-7
__device__ __forceinline__ float fast_sin(float x) {
    float n = rintf(x * 0.15915494309189535f);
    float r = fmaf(n, -6.2831854820251465f, x);   // x - n*hi(2pi)
    r = fmaf(n, 1.7484555e-7f, r);                // - n*lo(2pi), lo = 2pi-hi < 0
    return __sinf(r);
}

__device__ __forceinline__ float4 ldg4(const float* p) {
    return __ldg(reinterpret_cast<const float4*>(p));
}

// stream weight slab g (global index over 4 layers * 8 slabs) into wbuf[g&1]
__device__ __forceinline__ void issue_slab(const float* __restrict__ wh,
                                           float* wbuf, int g, int tid) {
    const float4* src = reinterpret_cast<const float4*>(wh + (size_t)g * KS * HIDDEN) + tid;
    float* dst = wbuf + (g & 1) * (KS * HIDDEN) + tid * 4;
    #pragma unroll
    for (int r = 0; r < (KS * HIDDEN / 4) / THREADS; r++)   // 8 x 16B per thread
        cp_async16(dst + r * THREADS * 4, src + r * THREADS);
    cp_commit();
}

__global__ void __launch_bounds__(THREADS, 1)
siren_fused_kernel(const float* __restrict__ coords,
                   const float* __restrict__ ow1, const float* __restrict__ ob1,
                   const float* __restrict__ ow2, const float* __restrict__ ob2,
                   const float* __restrict__ w0,  const float* __restrict__ b0,
                   const float* __restrict__ wh,  const float* __restrict__ bh,
                   const float* __restrict__ wf,  const float* __restrict__ bf,
                   float* __restrict__ out)
{
    extern __shared__ float smem[];
    float* xa   = smem;                       // [64][256]
    float* xb   = xa + MTILE * HIDDEN;        // [64][256]
    float* wbuf = xb + MTILE * HIDDEN;        // [2][KS*HIDDEN]
    float* omg  = wbuf + 2 * KS * HIDDEN;     // [64]
    float* cs   = omg + MTILE;                // [64][4]
    float* wfs  = cs + MTILE * 4;             // [256]

    const int tid = threadIdx.x;
    const int mt  = tid >> 5;                 // warp id -> m tile
    const int nt  = tid & 31;                 // lane    -> n tile
    const int m0  = mt * 8;
    const int cA  = nt * 4;                   // split-n: conflict-free LDS.128
    const int cB  = 128 + nt * 4;
    const long base = (long)blockIdx.x * MTILE;

    // kick off first weight slab ASAP (overlaps omega/layer0)
    issue_slab(wh, wbuf, 0, tid);

    // coords tile (64x4 = 256 floats) and final-layer weights to smem
    cs[tid]  = coords[base * 4 + tid];
    wfs[tid] = wf[tid];
    __syncthreads();

    // ---- omega predictor: 4 -> 64 relu -> 1 sigmoid (threads 0..63) ----
    if (tid < MTILE) {
        float c0 = cs[tid * 4 + 0], c1 = cs[tid * 4 + 1];
        float c2 = cs[tid * 4 + 2], c3 = cs[tid * 4 + 3];
        float s = __ldg(ob2);
        #pragma unroll 4
        for (int j = 0; j < 64; j++) {
            float h = __ldg(&ow1[j]) * c0;
            h = fmaf(__ldg(&ow1[64  + j]), c1, h);
            h = fmaf(__ldg(&ow1[128 + j]), c2, h);
            h = fmaf(__ldg(&ow1[192 + j]), c3, h);
            h += __ldg(&ob1[j]);
            h = fmaxf(h, 0.0f);
            s = fmaf(h, __ldg(&ow2[j]), s);
        }
        float sig = 1.0f / (1.0f + __expf(-s));
        omg[tid] = 10.0f + 90.0f * sig;
    }
    __syncthreads();

    float accA[8][4], accB[8][4];

    // ---- SIREN layer 0: x = sin(omega * (coords @ w0 + b0)), K=4 ----
    {
        #pragma unroll
        for (int i = 0; i < 8; i++)
            #pragma unroll
            for (int j = 0; j < 4; j++) { accA[i][j] = 0.0f; accB[i][j] = 0.0f; }
        #pragma unroll
        for (int k = 0; k < 4; k++) {
            float4 bA = ldg4(&w0[k * HIDDEN + cA]);
            float4 bB = ldg4(&w0[k * HIDDEN + cB]);
            #pragma unroll
            for (int i = 0; i < 8; i++) {
                float a = cs[(m0 + i) * 4 + k];
                accA[i][0] = fmaf(a, bA.x, accA[i][0]);
                accA[i][1] = fmaf(a, bA.y, accA[i][1]);
                accA[i][2] = fmaf(a, bA.z, accA[i][2]);
                accA[i][3] = fmaf(a, bA.w, accA[i][3]);
                accB[i][0] = fmaf(a, bB.x, accB[i][0]);
                accB[i][1] = fmaf(a, bB.y, accB[i][1]);
                accB[i][2] = fmaf(a, bB.z, accB[i][2]);
                accB[i][3] = fmaf(a, bB.w, accB[i][3]);
            }
        }
        float4 biA = ldg4(&b0[cA]);
        float4 biB = ldg4(&b0[cB]);
        #pragma unroll
        for (int i = 0; i < 8; i++) {
            float om = omg[m0 + i];
            float4 vA, vB;
            vA.x = fast_sin(om * (accA[i][0] + biA.x));
            vA.y = fast_sin(om * (accA[i][1] + biA.y));
            vA.z = fast_sin(om * (accA[i][2] + biA.z));
            vA.w = fast_sin(om * (accA[i][3] + biA.w));
            vB.x = fast_sin(om * (accB[i][0] + biB.x));
            vB.y = fast_sin(om * (accB[i][1] + biB.y));
            vB.z = fast_sin(om * (accB[i][2] + biB.z));
            vB.w = fast_sin(om * (accB[i][3] + biB.w));
            *reinterpret_cast<float4*>(&xa[(m0 + i) * HIDDEN + cA]) = vA;
            *reinterpret_cast<float4*>(&xa[(m0 + i) * HIDDEN + cB]) = vB;
        }
    }
    __syncthreads();

    // ---- 4 hidden layers: x = sin(omega * (x @ wh[l] + bh[l])) ----
    float* xin = xa;
    float* xout = xb;
    #pragma unroll 1
    for (int l = 0; l < NHL; l++) {
        #pragma unroll
        for (int i = 0; i < 8; i++)
            #pragma unroll
            for (int j = 0; j < 4; j++) { accA[i][j] = 0.0f; accB[i][j] = 0.0f; }

        #pragma unroll 1
        for (int s = 0; s < NSLAB; s++) {
            int g = l * NSLAB + s;
            if (g + 1 < NHL * NSLAB) {
                issue_slab(wh, wbuf, g + 1, tid);
                cp_wait<1>();
            } else {
                cp_wait<0>();
            }
            __syncthreads();
            const float* wb = wbuf + (g & 1) * (KS * HIDDEN);
            const float* xk = &xin[m0 * HIDDEN + s * KS];

            #pragma unroll 2
            for (int kq = 0; kq < KS / 4; kq++) {
                float4 a[8];
                #pragma unroll
                for (int i = 0; i < 8; i++)
                    a[i] = *reinterpret_cast<const float4*>(xk + i * HIDDEN + kq * 4);
                #pragma unroll
                for (int kk = 0; kk < 4; kk++) {
                    float4 bA = *reinterpret_cast<const float4*>(&wb[(kq * 4 + kk) * HIDDEN + cA]);
                    float4 bB = *reinterpret_cast<const float4*>(&wb[(kq * 4 + kk) * HIDDEN + cB]);
                    #pragma unroll
                    for (int i = 0; i < 8; i++) {
                        float av = (kk == 0) ? a[i].x : (kk == 1) ? a[i].y
                                 : (kk == 2) ? a[i].z : a[i].w;
                        accA[i][0] = fmaf(av, bA.x, accA[i][0]);
                        accA[i][1] = fmaf(av, bA.y, accA[i][1]);
                        accA[i][2] = fmaf(av, bA.z, accA[i][2]);
                        accA[i][3] = fmaf(av, bA.w, accA[i][3]);
                        accB[i][0] = fmaf(av, bB.x, accB[i][0]);
                        accB[i][1] = fmaf(av, bB.y, accB[i][1]);
                        accB[i][2] = fmaf(av, bB.z, accB[i][2]);
                        accB[i][3] = fmaf(av, bB.w, accB[i][3]);
                    }
                }
            }
            __syncthreads();
        }

        float4 bhA = ldg4(&bh[l * HIDDEN + cA]);
        float4 bhB = ldg4(&bh[l * HIDDEN + cB]);
        #pragma unroll
        for (int i = 0; i < 8; i++) {
            float om = omg[m0 + i];
            float4 vA, vB;
            vA.x = fast_sin(om * (accA[i][0] + bhA.x));
            vA.y = fast_sin(om * (accA[i][1] + bhA.y));
            vA.z = fast_sin(om * (accA[i][2] + bhA.z));
            vA.w = fast_sin(om * (accA[i][3] + bhA.w));
            vB.x = fast_sin(om * (accB[i][0] + bhB.x));
            vB.y = fast_sin(om * (accB[i][1] + bhB.y));
            vB.z = fast_sin(om * (accB[i][2] + bhB.z));
            vB.w = fast_sin(om * (accB[i][3] + bhB.w));
            *reinterpret_cast<float4*>(&xout[(m0 + i) * HIDDEN + cA]) = vA;
            *reinterpret_cast<float4*>(&xout[(m0 + i) * HIDDEN + cB]) = vB;
        }
        __syncthreads();
        float* t = xin; xin = xout; xout = t;
    }

    // ---- head: out[m] = x[m] @ wf + bf  (one warp per 8 points) ----
    {
        const int w = tid >> 5, lane = tid & 31;
        const float bfv = __ldg(bf);
        const float4* wr = reinterpret_cast<const float4*>(&wfs[lane * 8]);
        float4 w1 = wr[0], w2 = wr[1];
        #pragma unroll
        for (int p = 0; p < 8; p++) {
            int m = w * 8 + p;
            const float4* xr = reinterpret_cast<const float4*>(&xin[m * HIDDEN + lane * 8]);
            float4 x1 = xr[0], x2 = xr[1];
            float par = x1.x * w1.x + x1.y * w1.y + x1.z * w1.z + x1.w * w1.w
                      + x2.x * w2.x + x2.y * w2.y + x2.z * w2.z + x2.w * w2.w;
            #pragma unroll
            for (int off = 16; off > 0; off >>= 1)
                par += __shfl_xor_sync(0xffffffff, par, off);
            if (lane == 0) out[base + m] = par + bfv;
        }
    }
}

extern "C" void kernel_launch(void* const* d_in, const int* in_sizes, int n_in,
                              void* d_out, int out_size)
{
    const float* coords = (const float*)d_in[0];
    const float* ow1    = (const float*)d_in[1];
    const float* ob1    = (const float*)d_in[2];
    const float* ow2    = (const float*)d_in[3];
    const float* ob2    = (const float*)d_in[4];
    const float* w0     = (const float*)d_in[5];
    const float* b0     = (const float*)d_in[6];
    const float* wh     = (const float*)d_in[7];
    const float* bh     = (const float*)d_in[8];
    const float* wf     = (const float*)d_in[9];
    const float* bf     = (const float*)d_in[10];
    float* out = (float*)d_out;

    int n = in_sizes[0] / 4;                 // number of points
    int grid = n / MTILE;
    size_t smem_bytes = (size_t)SMEM_FLOATS * sizeof(float);   // ~194 KB

    cudaFuncSetAttribute(siren_fused_kernel,
                         cudaFuncAttributeMaxDynamicSharedMemorySize,
                         (int)smem_bytes);
    siren_fused_kernel<<<grid, THREADS, smem_bytes>>>(
        coords, ow1, ob1, ow2, ob2, w0, b0, wh, bh, wf, bf, out);
}

// round 2
// speedup vs baseline: 1.1842x; 1.1842x over previous
#include <cuda_runtime.h>
#include <cstdint>

#define HIDDEN   256
#define NHL      4
#define MTILE    64
#define KS       32
#define NSLAB    8          // HIDDEN / KS
#define THREADS  256

// smem layout (floats): xa[64*256] xb[64*256] wbuf[2*32*256] omg[64] cs[64*4] wfs[256]
#define SMEM_FLOATS (MTILE*HIDDEN*2 + 2*KS*HIDDEN + MTILE + MTILE*4 + HIDDEN)

__device__ __forceinline__ void cp_async16(float* dst, const float4* src) {
    uint32_t s = (uint32_t)__cvta_generic_to_shared(dst);
    asm volatile("cp.async.cg.shared.global [%0], [%1], 16;\n" :: "r"(s), "l"(src));
}
__device__ __forceinline__ void cp_commit() { asm volatile("cp.async.commit_group;\n" ::); }
template<int W> __device__ __forceinline__ void cp_wait() {
    asm volatile("cp.async.wait_group %0;\n" :: "n"(W));
}

// ---- packed fp32x2 helpers (FFMA2 path, ptxas never emits from C++) ----
__device__ __forceinline__ void fma2(uint64_t& d, uint64_t a, uint64_t b) {
    asm volatile("fma.rn.f32x2 %0, %1, %2, %0;" : "+l"(d) : "l"(a), "l"(b));
}
__device__ __forceinline__ uint64_t dup2(float x) {
    uint64_t d; asm("mov.b64 %0, {%1, %1};" : "=l"(d) : "f"(x)); return d;
}
__device__ __forceinline__ void unpack2(float& lo, float& hi, uint64_t v) {
    asm("mov.b64 {%0, %1}, %2;" : "=f"(lo), "=f"(hi) : "l"(v));
}

// sin with Cody-Waite range reduction to [-pi,pi]; abs err ~3e-7
__device__ __forceinline__ float fast_sin(float x) {
    float n = rintf(x * 0.15915494309189535f);
    float r = fmaf(n, -6.2831854820251465f, x);
    r = fmaf(n, 1.7484555e-7f, r);
    return __sinf(r);
}

__device__ __forceinline__ float4 ldg4(const float* p) {
    return __ldg(reinterpret_cast<const float4*>(p));
}

// stream weight slab g (global index over 4 layers * 8 slabs) into wbuf[g&1]
__device__ __forceinline__ void issue_slab(const float* __restrict__ wh,
                                           float* wbuf, int g, int tid) {
    const float4* src = reinterpret_cast<const float4*>(wh + (size_t)g * KS * HIDDEN) + tid;
    float* dst = wbuf + (g & 1) * (KS * HIDDEN) + tid * 4;
    #pragma unroll
    for (int r = 0; r < (KS * HIDDEN / 4) / THREADS; r++)
        cp_async16(dst + r * THREADS * 4, src + r * THREADS);
    cp_commit();
}

__global__ void __launch_bounds__(THREADS, 1)
siren_fused_kernel(const float* __restrict__ coords,
                   const float* __restrict__ ow1, const float* __restrict__ ob1,
                   const float* __restrict__ ow2, const float* __restrict__ ob2,
                   const float* __restrict__ w0,  const float* __restrict__ b0,
                   const float* __restrict__ wh,  const float* __restrict__ bh,
                   const float* __restrict__ wf,  const float* __restrict__ bf,
                   float* __restrict__ out)
{
    extern __shared__ float smem[];
    float* xa   = smem;                       // [64][256]
    float* xb   = xa + MTILE * HIDDEN;        // [64][256]
    float* wbuf = xb + MTILE * HIDDEN;        // [2][KS*HIDDEN]
    float* omg  = wbuf + 2 * KS * HIDDEN;     // [64]
    float* cs   = omg + MTILE;                // [64][4]
    float* wfs  = cs + MTILE * 4;             // [256]

    const int tid = threadIdx.x;
    const int mt  = tid >> 5;                 // warp id -> m tile
    const int nt  = tid & 31;                 // lane    -> n tile
    const int m0  = mt * 8;
    const int cA  = nt * 4;                   // split-n: conflict-free LDS.128
    const int cB  = 128 + nt * 4;
    const long base = (long)blockIdx.x * MTILE;

    issue_slab(wh, wbuf, 0, tid);

    cs[tid]  = coords[base * 4 + tid];
    wfs[tid] = wf[tid];
    __syncthreads();

    // ---- omega predictor: 4 -> 64 relu -> 1 sigmoid (threads 0..63) ----
    if (tid < MTILE) {
        float c0 = cs[tid * 4 + 0], c1 = cs[tid * 4 + 1];
        float c2 = cs[tid * 4 + 2], c3 = cs[tid * 4 + 3];
        float s = __ldg(ob2);
        #pragma unroll 4
        for (int j = 0; j < 64; j++) {
            float h = __ldg(&ow1[j]) * c0;
            h = fmaf(__ldg(&ow1[64  + j]), c1, h);
            h = fmaf(__ldg(&ow1[128 + j]), c2, h);
            h = fmaf(__ldg(&ow1[192 + j]), c3, h);
            h += __ldg(&ob1[j]);
            h = fmaxf(h, 0.0f);
            s = fmaf(h, __ldg(&ow2[j]), s);
        }
        float sig = 1.0f / (1.0f + __expf(-s));
        omg[tid] = 10.0f + 90.0f * sig;
    }
    __syncthreads();

    // ---- SIREN layer 0: x = sin(omega * (coords @ w0 + b0)), K=4 (scalar, tiny) ----
    {
        float accA[8][4], accB[8][4];
        #pragma unroll
        for (int i = 0; i < 8; i++)
            #pragma unroll
            for (int j = 0; j < 4; j++) { accA[i][j] = 0.0f; accB[i][j] = 0.0f; }
        #pragma unroll
        for (int k = 0; k < 4; k++) {
            float4 bA = ldg4(&w0[k * HIDDEN + cA]);
            float4 bB = ldg4(&w0[k * HIDDEN + cB]);
            #pragma unroll
            for (int i = 0; i < 8; i++) {
                float a = cs[(m0 + i) * 4 + k];
                accA[i][0] = fmaf(a, bA.x, accA[i][0]);
                accA[i][1] = fmaf(a, bA.y, accA[i][1]);
                accA[i][2] = fmaf(a, bA.z, accA[i][2]);
                accA[i][3] = fmaf(a, bA.w, accA[i][3]);
                accB[i][0] = fmaf(a, bB.x, accB[i][0]);
                accB[i][1] = fmaf(a, bB.y, accB[i][1]);
                accB[i][2] = fmaf(a, bB.z, accB[i][2]);
                accB[i][3] = fmaf(a, bB.w, accB[i][3]);
            }
        }
        float4 biA = ldg4(&b0[cA]);
        float4 biB = ldg4(&b0[cB]);
        #pragma unroll
        for (int i = 0; i < 8; i++) {
            float om = omg[m0 + i];
            float4 vA, vB;
            vA.x = fast_sin(om * (accA[i][0] + biA.x));
            vA.y = fast_sin(om * (accA[i][1] + biA.y));
            vA.z = fast_sin(om * (accA[i][2] + biA.z));
            vA.w = fast_sin(om * (accA[i][3] + biA.w));
            vB.x = fast_sin(om * (accB[i][0] + biB.x));
            vB.y = fast_sin(om * (accB[i][1] + biB.y));
            vB.z = fast_sin(om * (accB[i][2] + biB.z));
            vB.w = fast_sin(om * (accB[i][3] + biB.w));
            *reinterpret_cast<float4*>(&xa[(m0 + i) * HIDDEN + cA]) = vA;
            *reinterpret_cast<float4*>(&xa[(m0 + i) * HIDDEN + cB]) = vB;
        }
    }
    __syncthreads();

    // ---- 4 hidden layers: x = sin(omega * (x @ wh[l] + bh[l])), FFMA2 mainloop ----
    float* xin = xa;
    float* xout = xb;
    #pragma unroll 1
    for (int l = 0; l < NHL; l++) {
        // acc pairs: [i][0] = cols (cA,cA+1), [i][1] = cols (cA+2,cA+3); same for B half
        uint64_t accA[8][2], accB[8][2];
        #pragma unroll
        for (int i = 0; i < 8; i++) {
            accA[i][0] = 0ull; accA[i][1] = 0ull;
            accB[i][0] = 0ull; accB[i][1] = 0ull;
        }

        #pragma unroll 1
        for (int s = 0; s < NSLAB; s++) {
            int g = l * NSLAB + s;
            if (g + 1 < NHL * NSLAB) {
                issue_slab(wh, wbuf, g + 1, tid);
                cp_wait<1>();
            } else {
                cp_wait<0>();
            }
            __syncthreads();
            const float* wb = wbuf + (g & 1) * (KS * HIDDEN);
            const float* xk = &xin[m0 * HIDDEN + s * KS];

            #pragma unroll 2
            for (int kq = 0; kq < KS / 4; kq++) {
                float4 a[8];
                #pragma unroll
                for (int i = 0; i < 8; i++)
                    a[i] = *reinterpret_cast<const float4*>(xk + i * HIDDEN + kq * 4);
                #pragma unroll
                for (int kk = 0; kk < 4; kk++) {
                    ulonglong2 bA = *reinterpret_cast<const ulonglong2*>(&wb[(kq * 4 + kk) * HIDDEN + cA]);
                    ulonglong2 bB = *reinterpret_cast<const ulonglong2*>(&wb[(kq * 4 + kk) * HIDDEN + cB]);
                    #pragma unroll
                    for (int i = 0; i < 8; i++) {
                        float av = (kk == 0) ? a[i].x : (kk == 1) ? a[i].y
                                 : (kk == 2) ? a[i].z : a[i].w;
                        uint64_t ad = dup2(av);
                        fma2(accA[i][0], ad, bA.x);
                        fma2(accA[i][1], ad, bA.y);
                        fma2(accB[i][0], ad, bB.x);
                        fma2(accB[i][1], ad, bB.y);
                    }
                }
            }
            __syncthreads();
        }

        float4 bhA = ldg4(&bh[l * HIDDEN + cA]);
        float4 bhB = ldg4(&bh[l * HIDDEN + cB]);
        #pragma unroll
        for (int i = 0; i < 8; i++) {
            float om = omg[m0 + i];
            float a0, a1, a2, a3, b0v, b1v, b2v, b3v;
            unpack2(a0, a1, accA[i][0]);
            unpack2(a2, a3, accA[i][1]);
            unpack2(b0v, b1v, accB[i][0]);
            unpack2(b2v, b3v, accB[i][1]);
            float4 vA, vB;
            vA.x = fast_sin(om * (a0 + bhA.x));
            vA.y = fast_sin(om * (a1 + bhA.y));
            vA.z = fast_sin(om * (a2 + bhA.z));
            vA.w = fast_sin(om * (a3 + bhA.w));
            vB.x = fast_sin(om * (b0v + bhB.x));
            vB.y = fast_sin(om * (b1v + bhB.y));
            vB.z = fast_sin(om * (b2v + bhB.z));
            vB.w = fast_sin(om * (b3v + bhB.w));
            *reinterpret_cast<float4*>(&xout[(m0 + i) * HIDDEN + cA]) = vA;
            *reinterpret_cast<float4*>(&xout[(m0 + i) * HIDDEN + cB]) = vB;
        }
        __syncthreads();
        float* t = xin; xin = xout; xout = t;
    }

    // ---- head: out[m] = x[m] @ wf + bf  (one warp per 8 points) ----
    {
        const int w = tid >> 5, lane = tid & 31;
        const float bfv = __ldg(bf);
        const float4* wr = reinterpret_cast<const float4*>(&wfs[lane * 8]);
        float4 w1 = wr[0], w2 = wr[1];
        #pragma unroll
        for (int p = 0; p < 8; p++) {
            int m = w * 8 + p;
            const float4* xr = reinterpret_cast<const float4*>(&xin[m * HIDDEN + lane * 8]);
            float4 x1 = xr[0], x2 = xr[1];
            float par = x1.x * w1.x + x1.y * w1.y + x1.z * w1.z + x1.w * w1.w
                      + x2.x * w2.x + x2.y * w2.y + x2.z * w2.z + x2.w * w2.w;
            #pragma unroll
            for (int off = 16; off > 0; off >>= 1)
                par += __shfl_xor_sync(0xffffffff, par, off);
            if (lane == 0) out[base + m] = par + bfv;
        }
    }
}

extern "C" void kernel_launch(void* const* d_in, const int* in_sizes, int n_in,
                              void* d_out, int out_size)
{
    const float* coords = (const float*)d_in[0];
    const float* ow1    = (const float*)d_in[1];
    const float* ob1    = (const float*)d_in[2];
    const float* ow2    = (const float*)d_in[3];
    const float* ob2    = (const float*)d_in[4];
    const float* w0     = (const float*)d_in[5];
    const float* b0     = (const float*)d_in[6];
    const float* wh     = (const float*)d_in[7];
    const float* bh     = (const float*)d_in[8];
    const float* wf     = (const float*)d_in[9];
    const float* bf     = (const float*)d_in[10];
    float* out = (float*)d_out;

    int n = in_sizes[0] / 4;
    int grid = n / MTILE;
    size_t smem_bytes = (size_t)SMEM_FLOATS * sizeof(float);

    cudaFuncSetAttribute(siren_fused_kernel,
                         cudaFuncAttributeMaxDynamicSharedMemorySize,
                         (int)smem_bytes);
    siren_fused_kernel<<<grid, THREADS, smem_bytes>>>(
        coords, ow1, ob1, ow2, ob2, w0, b0, wh, bh, wf, bf, out);
}